// round 11
// baseline (speedup 1.0000x reference)
#include <cuda_runtime.h>
#include <cuda_bf16.h>
#include <math.h>

typedef unsigned int u32;

// Problem constants
#define BB   16
#define CC   256
#define HH   64
#define WWD  64
#define HWP  (HH*WWD)          // 4096
#define NTOK (BB*HWP)          // 65536
#define KD   128
#define PP   256
#define BN_EPS 1e-5f

// Scratch (device globals: allocation-free per harness rules)
__device__ __align__(256) __nv_bfloat16 g_k[PP*KD];
__device__ __align__(256) __nv_bfloat16 g_v[PP*KD];
__device__ __align__(256) __nv_bfloat16 g_q[(size_t)NTOK*KD];    // 16 MB
__device__ __align__(256) __nv_bfloat16 g_ao[(size_t)NTOK*KD];   // 16 MB
__device__ __align__(256) __nv_bfloat16 g_y[(size_t)BB*CC*HWP];  // 32 MB

// ---------------------------------------------------------------------------
// MMA / ldmatrix helpers (m16n8k16 bf16, fp32 accum) — maps proven in R5/R6
// ---------------------------------------------------------------------------
__device__ __forceinline__ u32 sm_u32(const void* p) {
    return (u32)__cvta_generic_to_shared(p);
}
__device__ __forceinline__ void ldsm_x4(u32* r, u32 a) {
    asm volatile("ldmatrix.sync.aligned.m8n8.x4.shared.b16 {%0,%1,%2,%3},[%4];"
                 : "=r"(r[0]),"=r"(r[1]),"=r"(r[2]),"=r"(r[3]) : "r"(a));
}
__device__ __forceinline__ void ldsm_x4t(u32* r, u32 a) {
    asm volatile("ldmatrix.sync.aligned.m8n8.x4.trans.shared.b16 {%0,%1,%2,%3},[%4];"
                 : "=r"(r[0]),"=r"(r[1]),"=r"(r[2]),"=r"(r[3]) : "r"(a));
}
__device__ __forceinline__ void mma16816(float* d, const u32* a, const u32* b) {
    asm volatile("mma.sync.aligned.m16n8k16.row.col.f32.bf16.bf16.f32 "
                 "{%0,%1,%2,%3},{%4,%5,%6,%7},{%8,%9},{%0,%1,%2,%3};"
                 : "+f"(d[0]),"+f"(d[1]),"+f"(d[2]),"+f"(d[3])
                 : "r"(a[0]),"r"(a[1]),"r"(a[2]),"r"(a[3]),"r"(b[0]),"r"(b[1]));
}
__device__ __forceinline__ void st_bf2(__nv_bfloat16* p, float a, float b) {
    *(__nv_bfloat162*)p = __floats2bfloat162_rn(a, b);
}
__device__ __forceinline__ void cpa16(void* dst, const void* src) {
    u32 d = sm_u32(dst);
    asm volatile("cp.async.cg.shared.global [%0], [%1], 16;" :: "r"(d), "l"(src));
}
#define CPA_COMMIT() asm volatile("cp.async.commit_group;")
#define CPA_WAIT0()  asm volatile("cp.async.wait_group 0;")

// ---------------------------------------------------------------------------
// K1: k = l2norm(m @ k_w^T + k_b), v = m @ v_w^T + v_b  (tiny, fp32 math)
// ---------------------------------------------------------------------------
__global__ __launch_bounds__(128) void kv_kernel(
    const float* __restrict__ m, const float* __restrict__ kw,
    const float* __restrict__ kb, const float* __restrict__ vw,
    const float* __restrict__ vb)
{
    __shared__ float mrow[KD];
    __shared__ float red[KD];
    int p = blockIdx.x;
    int d = threadIdx.x;
    mrow[d] = m[p*KD + d];
    __syncthreads();
    float kkv = kb[d], vvv = vb[d];
    #pragma unroll 4
    for (int j = 0; j < KD; j++) {
        float mj = mrow[j];
        kkv += mj * kw[d*KD + j];
        vvv += mj * vw[d*KD + j];
    }
    red[d] = kkv*kkv;
    __syncthreads();
    for (int s = 64; s > 0; s >>= 1) {
        if (d < s) red[d] += red[d+s];
        __syncthreads();
    }
    float scale = 1.f / fmaxf(sqrtf(red[0]), 1e-12f);
    g_k[p*KD + d] = __float2bfloat16(kkv * scale);
    g_v[p*KD + d] = __float2bfloat16(vvv);
}

// ---------------------------------------------------------------------------
// K2: qproj + L2 norm. Tile 128m x 128d, K=256. 512 threads (16 warps).
// Warp tile 16m x 64d: m_w=(w&7)*16, half=w>>3.
// ---------------------------------------------------------------------------
#define XS_LD 136
#define QW_LD 264
#define QP_PART (256*XS_LD + 128*QW_LD)              // bf16 units
#define QP_SMEM (QP_PART*2 + 128*4 + 256*4)

__global__ __launch_bounds__(512,1) void qproj_mma(
    const float* __restrict__ x, const float* __restrict__ qw,
    const float* __restrict__ qb)
{
    extern __shared__ __nv_bfloat16 smq[];
    __nv_bfloat16* Xs = smq;                 // [256 c][XS_LD m]
    __nv_bfloat16* Qw = smq + 256*XS_LD;     // [128 d][QW_LD c]
    float* qbs  = (float*)(smq + QP_PART);
    float* part = qbs + 128;                 // [2 halves][128 rows]
    int tid = threadIdx.x;
    int b = blockIdx.y, hw0 = blockIdx.x*128;
    const float* xb = x + (size_t)b*CC*HWP + hw0;

    for (int i = tid; i < 256*32; i += 512) {           // X: 256c x 128m
        int c = i >> 5, m4 = (i & 31) << 2;
        float4 v = *(const float4*)&xb[(size_t)c*HWP + m4];
        __nv_bfloat162* d2 = (__nv_bfloat162*)&Xs[c*XS_LD + m4];
        d2[0] = __floats2bfloat162_rn(v.x, v.y);
        d2[1] = __floats2bfloat162_rn(v.z, v.w);
    }
    for (int i = tid; i < 128*64; i += 512) {           // QW: 128d x 256c
        int d = i >> 6, c4 = (i & 63) << 2;
        float4 v = *(const float4*)&qw[d*CC + c4];
        __nv_bfloat162* d2 = (__nv_bfloat162*)&Qw[d*QW_LD + c4];
        d2[0] = __floats2bfloat162_rn(v.x, v.y);
        d2[1] = __floats2bfloat162_rn(v.z, v.w);
    }
    if (tid < 128) qbs[tid] = qb[tid];
    __syncthreads();

    int warp = tid >> 5, lane = tid & 31;
    int m_w = (warp & 7) * 16, half = warp >> 3, d0 = half * 64;
    float acc[8][4];
    #pragma unroll
    for (int nt = 0; nt < 8; nt++) { acc[nt][0]=acc[nt][1]=acc[nt][2]=acc[nt][3]=0.f; }

    u32 a_base = sm_u32(&Xs[((lane&7) + ((lane>>4)<<3))*XS_LD + m_w + ((lane>>3)&1)*8]);
    u32 b_base = sm_u32(&Qw[(d0 + (lane&7) + ((lane>>4)<<3))*QW_LD + ((lane>>3)&1)*8]);
    #pragma unroll
    for (int ks = 0; ks < 16; ks++) {
        u32 a[4];
        ldsm_x4t(a, a_base + ks*16*XS_LD*2);
        #pragma unroll
        for (int ntp = 0; ntp < 4; ntp++) {
            u32 bf[4];
            ldsm_x4(bf, b_base + (ntp*16*QW_LD + ks*16)*2);
            mma16816(acc[2*ntp],   a, bf);
            mma16816(acc[2*ntp+1], a, bf+2);
        }
    }
    // bias + partial L2 (this warp's 64 cols), quad-reduce, cross-half via smem
    int r = lane >> 2, col0 = (lane & 3)*2;
    float slo = 0.f, shi = 0.f;
    #pragma unroll
    for (int nt = 0; nt < 8; nt++) {
        float b0 = qbs[d0 + nt*8 + col0], b1 = qbs[d0 + nt*8 + col0 + 1];
        acc[nt][0] += b0; acc[nt][1] += b1; acc[nt][2] += b0; acc[nt][3] += b1;
        slo += acc[nt][0]*acc[nt][0] + acc[nt][1]*acc[nt][1];
        shi += acc[nt][2]*acc[nt][2] + acc[nt][3]*acc[nt][3];
    }
    slo += __shfl_xor_sync(~0u, slo, 1); slo += __shfl_xor_sync(~0u, slo, 2);
    shi += __shfl_xor_sync(~0u, shi, 1); shi += __shfl_xor_sync(~0u, shi, 2);
    if ((lane & 3) == 0) {
        part[half*128 + m_w + r]     = slo;
        part[half*128 + m_w + r + 8] = shi;
    }
    __syncthreads();
    float s_lo = 1.f/fmaxf(sqrtf(part[m_w+r]     + part[128+m_w+r]),     1e-12f);
    float s_hi = 1.f/fmaxf(sqrtf(part[m_w+r+8]   + part[128+m_w+r+8]),   1e-12f);
    size_t tok_lo = (size_t)b*HWP + hw0 + m_w + r;
    size_t tok_hi = tok_lo + 8;
    #pragma unroll
    for (int nt = 0; nt < 8; nt++) {
        st_bf2(&g_q[tok_lo*KD + d0 + nt*8 + col0], acc[nt][0]*s_lo, acc[nt][1]*s_lo);
        st_bf2(&g_q[tok_hi*KD + d0 + nt*8 + col0], acc[nt][2]*s_hi, acc[nt][3]*s_hi);
    }
}

// ---------------------------------------------------------------------------
// K3: fused attention, 128 tokens/CTA, 512 threads (16 warps).
// Phase1: S warp tile 16m x 128p (2 p-halves). exp in regs, P -> smem (bf16,
// unnormalized; overlays Q/K). Phase2: O warp tile 16m x 64d over K=256;
// normalize by rowsum at store.
// ---------------------------------------------------------------------------
#define PS_LD 264
#define A_Q   0
#define A_K   (128*XS_LD)
#define A_V   (128*XS_LD + 256*XS_LD)
#define A_END (128*XS_LD + 512*XS_LD)
#define AT_SMEM (A_END*2 + 256*4)

__global__ __launch_bounds__(512,1) void attn_mma()
{
    extern __shared__ __nv_bfloat16 sma[];
    __nv_bfloat16* Qs = sma + A_Q;           // [128][136]
    __nv_bfloat16* Ks = sma + A_K;           // [256][136]
    __nv_bfloat16* Vs = sma + A_V;           // [256][136]
    __nv_bfloat16* Ps = sma;                 // [128][264] overlays Qs+Ks
    float* part = (float*)(sma + A_END);     // [2][128]
    int tid = threadIdx.x;
    size_t n0 = (size_t)blockIdx.x * 128;
    int warp = tid >> 5, lane = tid & 31;
    int m_w = (warp & 7) * 16, half = warp >> 3;
    int r = lane >> 2, col0 = (lane & 3)*2;

    for (int i = tid; i < 128*16; i += 512) {
        int m = i >> 4, d8 = (i & 15) << 3;
        cpa16(&Qs[m*XS_LD + d8], &g_q[(n0+m)*KD + d8]);
    }
    for (int i = tid; i < 256*16; i += 512) {
        int p = i >> 4, d8 = (i & 15) << 3;
        cpa16(&Ks[p*XS_LD + d8], &g_k[p*KD + d8]);
        cpa16(&Vs[p*XS_LD + d8], &g_v[p*KD + d8]);
    }
    CPA_COMMIT();
    CPA_WAIT0();
    __syncthreads();

    // Phase 1: S = Q @ K^T, this warp: rows m_w..+15, cols p0..p0+127
    int p0 = half * 128;
    float acc[16][4];
    #pragma unroll
    for (int nt = 0; nt < 16; nt++) { acc[nt][0]=acc[nt][1]=acc[nt][2]=acc[nt][3]=0.f; }
    {
        u32 a_base = sm_u32(&Qs[(m_w + (lane&15))*XS_LD + ((lane>>4)&1)*8]);
        u32 b_base = sm_u32(&Ks[(p0 + (lane&7) + ((lane>>4)<<3))*XS_LD + ((lane>>3)&1)*8]);
        #pragma unroll
        for (int ks = 0; ks < 8; ks++) {
            u32 a[4];
            ldsm_x4(a, a_base + ks*16*2);
            #pragma unroll
            for (int ntp = 0; ntp < 8; ntp++) {
                u32 bf[4];
                ldsm_x4(bf, b_base + (ntp*16*XS_LD + ks*16)*2);
                mma16816(acc[2*ntp],   a, bf);
                mma16816(acc[2*ntp+1], a, bf+2);
            }
        }
    }
    // exp(clip) in regs + this-half row sums
    const float invT = 1.0f/0.07f;
    float slo = 0.f, shi = 0.f;
    #pragma unroll
    for (int nt = 0; nt < 16; nt++) {
        #pragma unroll
        for (int e = 0; e < 2; e++) {
            float pl = __expf(fminf(fmaxf(acc[nt][e]*invT,   -30.f), 30.f));
            float ph = __expf(fminf(fmaxf(acc[nt][2+e]*invT, -30.f), 30.f));
            acc[nt][e] = pl;   slo += pl;
            acc[nt][2+e] = ph; shi += ph;
        }
    }
    slo += __shfl_xor_sync(~0u, slo, 1); slo += __shfl_xor_sync(~0u, slo, 2);
    shi += __shfl_xor_sync(~0u, shi, 1); shi += __shfl_xor_sync(~0u, shi, 2);
    __syncthreads();                         // all warps done reading Qs/Ks
    if ((lane & 3) == 0) {
        part[half*128 + m_w + r]     = slo;
        part[half*128 + m_w + r + 8] = shi;
    }
    #pragma unroll
    for (int nt = 0; nt < 16; nt++) {
        st_bf2(&Ps[(m_w+r)*PS_LD + p0 + nt*8 + col0],   acc[nt][0], acc[nt][1]);
        st_bf2(&Ps[(m_w+r+8)*PS_LD + p0 + nt*8 + col0], acc[nt][2], acc[nt][3]);
    }
    __syncthreads();

    // Phase 2: O = P @ V, this warp: rows m_w..+15, dims d0..d0+63, K=256
    int d0 = half * 64;
    float oacc[8][4];
    #pragma unroll
    for (int nt = 0; nt < 8; nt++) { oacc[nt][0]=oacc[nt][1]=oacc[nt][2]=oacc[nt][3]=0.f; }
    {
        u32 a_base = sm_u32(&Ps[(m_w + (lane&15))*PS_LD + ((lane>>4)&1)*8]);
        u32 v_base = sm_u32(&Vs[((lane&7) + ((lane>>3)&1)*8)*XS_LD + d0 + ((lane>>4)&1)*8]);
        #pragma unroll
        for (int kt = 0; kt < 16; kt++) {
            u32 a[4];
            ldsm_x4(a, a_base + kt*16*2);
            #pragma unroll
            for (int ntp = 0; ntp < 4; ntp++) {
                u32 bf[4];
                ldsm_x4t(bf, v_base + (kt*16*XS_LD + ntp*16)*2);
                mma16816(oacc[2*ntp],   a, bf);
                mma16816(oacc[2*ntp+1], a, bf+2);
            }
        }
    }
    float ilo = 1.f / (part[m_w+r]   + part[128+m_w+r]);
    float ihi = 1.f / (part[m_w+r+8] + part[128+m_w+r+8]);
    size_t tok_lo = n0 + m_w + r, tok_hi = tok_lo + 8;
    #pragma unroll
    for (int nt = 0; nt < 8; nt++) {
        st_bf2(&g_ao[tok_lo*KD + d0 + nt*8 + col0], oacc[nt][0]*ilo, oacc[nt][1]*ilo);
        st_bf2(&g_ao[tok_hi*KD + d0 + nt*8 + col0], oacc[nt][2]*ihi, oacc[nt][3]*ihi);
    }
}

// ---------------------------------------------------------------------------
// K4: y[c][hw] tile 128c x 64hw, K=128. 256 threads, 4 CTAs/SM (32 warps).
// Warp tile 16c x 64hw.
// ---------------------------------------------------------------------------
#define OP_SMEM ((128*XS_LD + 64*XS_LD)*2 + 128*4)

__global__ __launch_bounds__(256,4) void oproj_mma(
    const float* __restrict__ ow, const float* __restrict__ ob)
{
    extern __shared__ __nv_bfloat16 smo[];
    __nv_bfloat16* OWs = smo;                 // [128 c][136 d]
    __nv_bfloat16* AOs = smo + 128*XS_LD;     // [64 hw][136 d]
    float* obs = (float*)(smo + 192*XS_LD);
    int tid = threadIdx.x;
    int c0 = blockIdx.x*128, hw0 = blockIdx.y*64, b = blockIdx.z;

    for (int i = tid; i < 64*16; i += 256) {
        int hw = i >> 4, d8 = (i & 15) << 3;
        cpa16(&AOs[hw*XS_LD + d8], &g_ao[((size_t)b*HWP + hw0 + hw)*KD + d8]);
    }
    CPA_COMMIT();
    for (int i = tid; i < 128*32; i += 256) {
        int c = i >> 5, d4 = (i & 31) << 2;
        float4 v = *(const float4*)&ow[(size_t)(c0+c)*KD + d4];
        __nv_bfloat162* d2 = (__nv_bfloat162*)&OWs[c*XS_LD + d4];
        d2[0] = __floats2bfloat162_rn(v.x, v.y);
        d2[1] = __floats2bfloat162_rn(v.z, v.w);
    }
    if (tid < 128) obs[tid] = ob[c0 + tid];
    CPA_WAIT0();
    __syncthreads();

    int warp = tid >> 5, lane = tid & 31;
    int c_w = warp * 16;
    float acc[8][4];
    #pragma unroll
    for (int nt = 0; nt < 8; nt++) { acc[nt][0]=acc[nt][1]=acc[nt][2]=acc[nt][3]=0.f; }
    u32 a_base = sm_u32(&OWs[(c_w + (lane&15))*XS_LD + ((lane>>4)&1)*8]);
    u32 b_base = sm_u32(&AOs[((lane&7) + ((lane>>4)<<3))*XS_LD + ((lane>>3)&1)*8]);
    #pragma unroll
    for (int ks = 0; ks < 8; ks++) {
        u32 a[4];
        ldsm_x4(a, a_base + ks*16*2);
        #pragma unroll
        for (int ntp = 0; ntp < 4; ntp++) {
            u32 bf[4];
            ldsm_x4(bf, b_base + (ntp*16*XS_LD + ks*16)*2);
            mma16816(acc[2*ntp],   a, bf);
            mma16816(acc[2*ntp+1], a, bf+2);
        }
    }
    int r = lane >> 2, col0 = (lane & 3)*2;
    int c_lo = c_w + r, c_hi = c_lo + 8;
    float b_lo = obs[c_lo], b_hi = obs[c_hi];
    size_t base_lo = ((size_t)b*CC + c0 + c_lo)*HWP + hw0;
    size_t base_hi = ((size_t)b*CC + c0 + c_hi)*HWP + hw0;
    #pragma unroll
    for (int nt = 0; nt < 8; nt++) {
        st_bf2(&g_y[base_lo + nt*8 + col0], acc[nt][0]+b_lo, acc[nt][1]+b_lo);
        st_bf2(&g_y[base_hi + nt*8 + col0], acc[nt][2]+b_hi, acc[nt][3]+b_hi);
    }
}

// ---------------------------------------------------------------------------
// K5: depthwise 3x3 (SAME) on y (bf16), BN1, exact GELU, residual, gamma, BN2.
// ---------------------------------------------------------------------------
__global__ __launch_bounds__(256) void final_kernel(
    const float* __restrict__ x, const float* __restrict__ dww,
    const float* __restrict__ bn1w, const float* __restrict__ bn1b,
    const float* __restrict__ bn2w, const float* __restrict__ bn2b,
    const float* __restrict__ gamma, float* __restrict__ out)
{
    __shared__ float tile[10][34];
    int bc = blockIdx.z;
    int c = bc & (CC-1);
    int h0 = blockIdx.y*8, w0 = blockIdx.x*32;
    int tx = threadIdx.x, ty = threadIdx.y;
    const __nv_bfloat16* yp = g_y + (size_t)bc*HWP;
    int tid = ty*32 + tx;
    for (int i = tid; i < 34*10; i += 256) {
        int yy = i / 34, xx = i - yy*34;
        int gh = h0 + yy - 1, gw = w0 + xx - 1;
        float v = 0.f;
        if (gh >= 0 && gh < HH && gw >= 0 && gw < WWD)
            v = __bfloat162float(yp[gh*WWD + gw]);
        tile[yy][xx] = v;
    }
    __syncthreads();

    float kern[9];
    #pragma unroll
    for (int i = 0; i < 9; i++) kern[i] = dww[c*9 + i];
    float conv = 0.f;
    #pragma unroll
    for (int kh = 0; kh < 3; kh++) {
        #pragma unroll
        for (int kw = 0; kw < 3; kw++) conv += tile[ty+kh][tx+kw] * kern[kh*3+kw];
    }
    float inv = rsqrtf(1.f + BN_EPS);
    float z = conv * (bn1w[c]*inv) + bn1b[c];
    float gl = 0.5f * z * (1.f + erff(z * 0.70710678118654752f));
    float yv = tile[ty+1][tx+1];
    float ot = yv + gl;                           // out + local
    int hw = (h0+ty)*WWD + (w0+tx);
    float xv = x[(size_t)bc*HWP + hw];
    out[(size_t)bc*HWP + hw] = (xv + gamma[c]*ot) * (bn2w[c]*inv) + bn2b[c];
}

// ---------------------------------------------------------------------------
extern "C" void kernel_launch(void* const* d_in, const int* in_sizes, int n_in,
                              void* d_out, int out_size)
{
    (void)in_sizes; (void)n_in; (void)out_size;
    const float* x    = (const float*)d_in[0];
    const float* m    = (const float*)d_in[1];
    const float* qw   = (const float*)d_in[2];
    const float* qb   = (const float*)d_in[3];
    const float* kw   = (const float*)d_in[4];
    const float* kb   = (const float*)d_in[5];
    const float* vw   = (const float*)d_in[6];
    const float* vb   = (const float*)d_in[7];
    const float* ow   = (const float*)d_in[8];
    const float* ob   = (const float*)d_in[9];
    const float* dww  = (const float*)d_in[10];
    const float* bn1w = (const float*)d_in[11];
    const float* bn1b = (const float*)d_in[12];
    const float* bn2w = (const float*)d_in[13];
    const float* bn2b = (const float*)d_in[14];
    const float* gam  = (const float*)d_in[15];
    float* out = (float*)d_out;

    cudaFuncSetAttribute(qproj_mma, cudaFuncAttributeMaxDynamicSharedMemorySize, QP_SMEM);
    cudaFuncSetAttribute(attn_mma,  cudaFuncAttributeMaxDynamicSharedMemorySize, AT_SMEM);
    cudaFuncSetAttribute(oproj_mma, cudaFuncAttributeMaxDynamicSharedMemorySize, OP_SMEM);

    kv_kernel<<<PP, KD>>>(m, kw, kb, vw, vb);
    qproj_mma<<<dim3(HWP/128, BB), 512, QP_SMEM>>>(x, qw, qb);
    attn_mma<<<NTOK/128, 512, AT_SMEM>>>();
    oproj_mma<<<dim3(CC/128, HWP/64, BB), 256, OP_SMEM>>>(ow, ob);
    final_kernel<<<dim3(WWD/32, HH/8, BB*CC), dim3(32,8)>>>(
        x, dww, bn1w, bn1b, bn2w, bn2b, gam, out);
}